// round 1
// baseline (speedup 1.0000x reference)
#include <cuda_runtime.h>

// C4ByteTransformer: 4 sequential carry-propagation steps.
// Key identity: softmax weights factorize as EA[a]*EB[b]*EC[c]/Z, and the
// output bins (a+b+c)&255 / carry (a+b+c>=256) reduce to a 256x256 linear
// convolution S[m] = sum_a EA[a]*EB[m-a] plus suffix sums.
// One persistent CTA (512 threads) runs all 4 steps with carry in SMEM.

#define NSTEP 4

__global__ __launch_bounds__(512, 1)
void c4_add_kernel(const float* __restrict__ a_emb,
                   const float* __restrict__ b_emb,
                   float* __restrict__ out) {
    __shared__ __align__(16) float EA[256];
    __shared__ __align__(16) float EBp[1024];   // EB at [255+b], zero padded
    __shared__ __align__(16) float Spart[4 * 512];
    __shared__ float Ssh[513];                  // Ssh[1+m] = S[m], Ssh[0]=0
    __shared__ float Tsh[2];                    // [0]=sum m<=255, [1]=sum m>=256
    __shared__ float csh[2];                    // carry state
    __shared__ float ECsh[2];

    const int tid  = threadIdx.x;
    const int lane = tid & 31;
    const int wid  = tid >> 5;

    // one-time init: zero EBp padding, carry0 = (1, 0)
    EBp[tid] = 0.f;
    EBp[512 + tid] = 0.f;
    if (tid == 0) { csh[0] = 1.f; csh[1] = 0.f; Ssh[0] = 0.f; }
    __syncthreads();

    for (int step = 0; step < NSTEP; ++step) {
        // ---- Phase A: exponentials + per-step resets ----
        if (tid < 256) {
            EA[tid] = __expf(10.f * a_emb[step * 256 + tid]);
        } else {
            int b = tid - 256;
            EBp[255 + b] = __expf(10.f * b_emb[step * 256 + b]);
        }
        if (tid == 0) {
            ECsh[0] = __expf(10.f * csh[0]);
            ECsh[1] = __expf(10.f * csh[1]);
            Tsh[0] = 0.f;
            Tsh[1] = 0.f;
        }
        __syncthreads();

        // ---- Phase B: convolution partials ----
        // thread = (as, mg): outputs m in [4*mg, 4*mg+3], a in [64*as, 64*as+63]
        // EBp index for (m, a): 255 + m - a. Sliding register window of 8
        // values (lo=EBp[J..J+3], hi=EBp[J+4..J+7]) advanced by one LDS.128
        // per 4-a block; EA loaded as broadcast LDS.128.
        const int as    = tid >> 7;
        const int mg    = tid & 127;
        const int m0    = mg << 2;
        const int abase = as << 6;
        const int J0    = 252 + m0 - abase;     // in [60, 760], 16B-aligned
        float4 lo = *(const float4*)&EBp[J0];
        float4 hi = *(const float4*)&EBp[J0 + 4];
        float s0 = 0.f, s1 = 0.f, s2 = 0.f, s3 = 0.f;
        #pragma unroll
        for (int k = 0; k < 16; ++k) {
            float4 ea = *(const float4*)&EA[abase + 4 * k];
            // acc[r] += ea[da] * w[3 + r - da], w[i] = EBp[J + i]
            s0 = fmaf(ea.x, lo.w, s0); s0 = fmaf(ea.y, lo.z, s0);
            s0 = fmaf(ea.z, lo.y, s0); s0 = fmaf(ea.w, lo.x, s0);
            s1 = fmaf(ea.x, hi.x, s1); s1 = fmaf(ea.y, lo.w, s1);
            s1 = fmaf(ea.z, lo.z, s1); s1 = fmaf(ea.w, lo.y, s1);
            s2 = fmaf(ea.x, hi.y, s2); s2 = fmaf(ea.y, hi.x, s2);
            s2 = fmaf(ea.z, lo.w, s2); s2 = fmaf(ea.w, lo.z, s2);
            s3 = fmaf(ea.x, hi.z, s3); s3 = fmaf(ea.y, hi.y, s3);
            s3 = fmaf(ea.z, hi.x, s3); s3 = fmaf(ea.w, lo.w, s3);
            if (k < 15) {           // slide window down by 4
                hi = lo;
                lo = *(const float4*)&EBp[J0 - 4 * (k + 1)];
            }
        }
        *(float4*)&Spart[as * 512 + m0] = make_float4(s0, s1, s2, s3);
        __syncthreads();

        // ---- Phase C: combine partials + block reductions ----
        float s = Spart[tid] + Spart[512 + tid] + Spart[1024 + tid] + Spart[1536 + tid];
        Ssh[1 + tid] = s;                       // S[m=tid]; S[511] = 0 naturally
        float r = s;
        #pragma unroll
        for (int off = 16; off > 0; off >>= 1)
            r += __shfl_down_sync(0xffffffffu, r, off);
        if (lane == 0) atomicAdd(&Tsh[wid >> 3], r);  // warps 0-7 -> low, 8-15 -> high
        __syncthreads();

        // ---- Phase D: outputs + new carry ----
        const float EC0   = ECsh[0], EC1 = ECsh[1];
        const float Tlow  = Tsh[0],  Thigh = Tsh[1];
        const float S255  = Ssh[256];           // S[255]
        const float invZ  = 1.0f / ((EC0 + EC1) * (Tlow + Thigh));
        if (tid < 256) {
            // c=0: m = d or d+256; c=1: m = d-1 or d+255
            float num = EC0 * (Ssh[1 + tid] + Ssh[257 + tid])
                      + EC1 * (Ssh[tid]     + Ssh[256 + tid]);
            out[step * 256 + tid] = num * invZ;
        }
        if (tid == 0) {
            csh[0] = (EC0 * Tlow  + EC1 * (Tlow  - S255)) * invZ;
            csh[1] = (EC0 * Thigh + EC1 * (Thigh + S255)) * invZ;
        }
        __syncthreads();
    }
}

extern "C" void kernel_launch(void* const* d_in, const int* in_sizes, int n_in,
                              void* d_out, int out_size) {
    const float* a_emb = (const float*)d_in[0];   // [4, 256]
    const float* b_emb = (const float*)d_in[1];   // [4, 256]
    float* out = (float*)d_out;                   // [4, 256]
    (void)in_sizes; (void)n_in; (void)out_size;
    c4_add_kernel<<<1, 512>>>(a_emb, b_emb, out);
}

// round 3
// speedup vs baseline: 1.4908x; 1.4908x over previous
#include <cuda_runtime.h>

// C4ByteTransformer: softmax weights factorize as EA[a]*EB[b]*EC[c]/Z, so each
// step reduces to a 256x256 linear convolution S[m] = sum_a EA[a]*EB[m-a]
// (carry-independent!) plus a tiny carry-dependent epilogue.
// R2: the 4 convolutions run in PARALLEL on 4 CTAs; the last-arriving CTA
// runs the sequential 4-step carry chain + writes all outputs.

__device__ float g_S[4][513];   // g_S[s][0]=0, g_S[s][1+m]=S_s[m]
__device__ float g_T[4][2];     // [s][0]=sum_{m<256} S, [s][1]=sum_{m>=256} S
__device__ int   g_count = 0;

__global__ __launch_bounds__(1024, 1)
void c4_conv_kernel(const float* __restrict__ a_emb,
                    const float* __restrict__ b_emb,
                    float* __restrict__ out) {
    __shared__ __align__(16) float EA[256];
    __shared__ __align__(16) float EBp[1024];   // EB at [255+b], zero padded
    __shared__ __align__(16) float Spart[8 * 512];
    __shared__ float Tsh[2];
    __shared__ float EC0s[4], EC1s[4], iZs[4];
    __shared__ int   last_flag;

    const int tid  = threadIdx.x;
    const int step = blockIdx.x;
    const int lane = tid & 31;
    const int wid  = tid >> 5;

    // ---- Phase A: exponentials (each thread writes exactly one EBp slot) ----
    if (tid < 256) EA[tid] = __expf(10.f * a_emb[step * 256 + tid]);
    float vb = 0.f;
    if (tid >= 255 && tid < 511) vb = __expf(10.f * b_emb[step * 256 + tid - 255]);
    EBp[tid] = vb;                               // zeros outside [255,511)
    if (tid == 0) { Tsh[0] = 0.f; Tsh[1] = 0.f; }
    __syncthreads();

    // ---- Phase B: convolution partials ----
    // thread = (as, mg): outputs m in [4*mg, 4*mg+3], a in [32*as, 32*as+31].
    // EBp index for (m, a) = 255 + m - a. Register window of 8 floats slides
    // down by 4 per iteration (one LDS.128); EA via broadcast LDS.128.
    const int as    = tid >> 7;                  // 0..7
    const int mg    = tid & 127;
    const int m0    = mg << 2;
    const int abase = as << 5;                   // 32 a-values per slice
    const int J0    = 252 + m0 - abase;          // in [28, 760], 16B aligned
    float4 lo = *(const float4*)&EBp[J0];
    float4 hi = *(const float4*)&EBp[J0 + 4];
    float s0 = 0.f, s1 = 0.f, s2 = 0.f, s3 = 0.f;
    #pragma unroll
    for (int k = 0; k < 8; ++k) {
        float4 ea = *(const float4*)&EA[abase + 4 * k];
        // acc[r] += ea[da] * w[3 + r - da], w[i] = EBp[J0 - 4k + i]
        s0 = fmaf(ea.x, lo.w, s0); s0 = fmaf(ea.y, lo.z, s0);
        s0 = fmaf(ea.z, lo.y, s0); s0 = fmaf(ea.w, lo.x, s0);
        s1 = fmaf(ea.x, hi.x, s1); s1 = fmaf(ea.y, lo.w, s1);
        s1 = fmaf(ea.z, lo.z, s1); s1 = fmaf(ea.w, lo.y, s1);
        s2 = fmaf(ea.x, hi.y, s2); s2 = fmaf(ea.y, hi.x, s2);
        s2 = fmaf(ea.z, lo.w, s2); s2 = fmaf(ea.w, lo.z, s2);
        s3 = fmaf(ea.x, hi.z, s3); s3 = fmaf(ea.y, hi.y, s3);
        s3 = fmaf(ea.z, hi.x, s3); s3 = fmaf(ea.w, lo.w, s3);
        if (k < 7) {                             // slide window down by 4
            hi = lo;
            lo = *(const float4*)&EBp[J0 - 4 * (k + 1)];
        }
    }
    *(float4*)&Spart[as * 512 + m0] = make_float4(s0, s1, s2, s3);
    __syncthreads();

    // ---- Phase C: combine partials, publish S + sums to global ----
    if (tid < 512) {
        float s = 0.f;
        #pragma unroll
        for (int j = 0; j < 8; ++j) s += Spart[j * 512 + tid];
        g_S[step][1 + tid] = s;                  // S[m=tid]; S[511]=0 naturally
        float r = s;
        #pragma unroll
        for (int off = 16; off > 0; off >>= 1)
            r += __shfl_down_sync(0xffffffffu, r, off);
        if (lane == 0) atomicAdd(&Tsh[wid >> 3], r);  // warps 0-7 low, 8-15 high
    } else if (tid == 512) {
        g_S[step][0] = 0.f;
    }
    __syncthreads();
    if (tid == 0) {
        g_T[step][0] = Tsh[0];
        g_T[step][1] = Tsh[1];
    }
    __threadfence();                             // publish g_S/g_T to device
    __syncthreads();
    if (tid == 0) {
        int old = atomicAdd(&g_count, 1);
        last_flag = (old == 3);
    }
    __syncthreads();
    if (!last_flag) return;

    // ---- Epilogue (last-arriving CTA only): carry chain + outputs ----
    __threadfence();                             // acquire others' g_S/g_T
    if (tid == 0) {
        float c0 = 1.f, c1 = 0.f;                // carry0 = (1, 0)
        #pragma unroll
        for (int s = 0; s < 4; ++s) {
            float Tlow = g_T[s][0], Thigh = g_T[s][1];
            float S255 = g_S[s][256];            // S[255]
            float E0 = __expf(10.f * c0), E1 = __expf(10.f * c1);
            float iZ = 1.0f / ((E0 + E1) * (Tlow + Thigh));
            EC0s[s] = E0; EC1s[s] = E1; iZs[s] = iZ;
            c0 = (E0 * Tlow  + E1 * (Tlow  - S255)) * iZ;
            c1 = (E0 * Thigh + E1 * (Thigh + S255)) * iZ;
        }
        g_count = 0;                             // reset for next graph replay
    }
    __syncthreads();
    {
        const int s = tid >> 8, d = tid & 255;   // 1024 threads = 4x256 outputs
        const float* gS = g_S[s];
        // c=0: bins m=d and m=d+256 ; c=1: bins m=d-1 and m=d+255
        float num = EC0s[s] * (gS[1 + d] + gS[257 + d])
                  + EC1s[s] * (gS[d]     + gS[256 + d]);
        out[s * 256 + d] = num * iZs[s];
    }
}

extern "C" void kernel_launch(void* const* d_in, const int* in_sizes, int n_in,
                              void* d_out, int out_size) {
    const float* a_emb = (const float*)d_in[0];   // [4, 256]
    const float* b_emb = (const float*)d_in[1];   // [4, 256]
    float* out = (float*)d_out;                   // [4, 256]
    (void)in_sizes; (void)n_in; (void)out_size;
    c4_conv_kernel<<<4, 1024>>>(a_emb, b_emb, out);
}

// round 11
// speedup vs baseline: 1.5018x; 1.0074x over previous
#include <cuda_runtime.h>
#include <cstdint>

// C4ByteTransformer: softmax weights factorize as EA[a]*EB[b]*EC[c]/Z, so each
// step reduces to a 256x256 linear convolution S[m] = sum_a EA[a]*EB[m-a]
// (carry-independent) plus a tiny carry-dependent epilogue.
// R3..R10: 4 CTAs in ONE CLUSTER. Each CTA does its step's conv into local
// SMEM and broadcasts only 3 scalars (Tlow, Thigh, S[255]) to all peers via
// DSMEM. After one barrier.cluster, every CTA redundantly runs the 40-flop
// carry chain and writes its own step's outputs. No gmem rendezvous or fences.

__device__ __forceinline__ uint32_t smem_u32(const void* p) {
    uint32_t a;
    asm("{ .reg .u64 t; cvta.to.shared.u64 t, %1; cvt.u32.u64 %0, t; }"
        : "=r"(a) : "l"(p));
    return a;
}

__global__ __launch_bounds__(1024, 1) __cluster_dims__(4, 1, 1)
void c4_cluster_kernel(const float* __restrict__ a_emb,
                       const float* __restrict__ b_emb,
                       float* __restrict__ out) {
    __shared__ __align__(16) float EA[256];
    __shared__ __align__(16) float EBp[1024];    // EB at [255+b], zero padded
    __shared__ __align__(16) float Spart[8 * 512];
    __shared__ __align__(16) float S[513];       // S[0]=0, S[1+m]=S_step[m]
    __shared__ __align__(16) float trip[4][3];   // [s] = {Tlow, Thigh, S255}
    __shared__ float Tsh[2];
    __shared__ float ECiZ[3];                    // my step's {EC0, EC1, iZ}

    const int tid  = threadIdx.x;
    const int step = blockIdx.x;                 // == cluster rank
    const int lane = tid & 31;
    const int wid  = tid >> 5;

    // ---- Phase A: exponentials (each thread writes exactly one EBp slot) ----
    if (tid < 256) EA[tid] = __expf(10.f * a_emb[step * 256 + tid]);
    float vb = 0.f;
    if (tid >= 255 && tid < 511) vb = __expf(10.f * b_emb[step * 256 + tid - 255]);
    EBp[tid] = vb;                               // zeros outside [255,510]
    if (tid == 0) { Tsh[0] = 0.f; Tsh[1] = 0.f; S[0] = 0.f; }
    __syncthreads();

    // ---- Phase B: convolution partials ----
    // thread = (as, mg): outputs m in [4*mg, 4*mg+3], a in [32*as, 32*as+31].
    // EBp index for (m, a) = 255 + m - a. 8-float register window slides down
    // by 4 per iteration (one LDS.128); EA via broadcast LDS.128.
    const int as    = tid >> 7;                  // 0..7
    const int mg    = tid & 127;
    const int m0    = mg << 2;
    const int abase = as << 5;
    const int J0    = 252 + m0 - abase;          // in [28, 760], 16B aligned
    float4 lo = *(const float4*)&EBp[J0];
    float4 hi = *(const float4*)&EBp[J0 + 4];
    float s0 = 0.f, s1 = 0.f, s2 = 0.f, s3 = 0.f;
    #pragma unroll
    for (int k = 0; k < 8; ++k) {
        float4 ea = *(const float4*)&EA[abase + 4 * k];
        s0 = fmaf(ea.x, lo.w, s0); s0 = fmaf(ea.y, lo.z, s0);
        s0 = fmaf(ea.z, lo.y, s0); s0 = fmaf(ea.w, lo.x, s0);
        s1 = fmaf(ea.x, hi.x, s1); s1 = fmaf(ea.y, lo.w, s1);
        s1 = fmaf(ea.z, lo.z, s1); s1 = fmaf(ea.w, lo.y, s1);
        s2 = fmaf(ea.x, hi.y, s2); s2 = fmaf(ea.y, hi.x, s2);
        s2 = fmaf(ea.z, lo.w, s2); s2 = fmaf(ea.w, lo.z, s2);
        s3 = fmaf(ea.x, hi.z, s3); s3 = fmaf(ea.y, hi.y, s3);
        s3 = fmaf(ea.z, hi.x, s3); s3 = fmaf(ea.w, lo.w, s3);
        if (k < 7) {                             // slide window down by 4
            hi = lo;
            lo = *(const float4*)&EBp[J0 - 4 * (k + 1)];
        }
    }
    *(float4*)&Spart[as * 512 + m0] = make_float4(s0, s1, s2, s3);
    __syncthreads();

    // ---- Phase C: combine partials into local S + block reductions ----
    if (tid < 512) {
        float s = 0.f;
        #pragma unroll
        for (int j = 0; j < 8; ++j) s += Spart[j * 512 + tid];
        S[1 + tid] = s;                          // S[m=tid]; S[511]=0 naturally
        float r = s;
        #pragma unroll
        for (int off = 16; off > 0; off >>= 1)
            r += __shfl_down_sync(0xffffffffu, r, off);
        if (lane == 0) atomicAdd(&Tsh[wid >> 3], r);  // warps 0-7 low, 8-15 high
    }
    __syncthreads();

    // ---- Phase D: broadcast my {Tlow, Thigh, S255} to every cluster CTA ----
    if (tid == 0) {
        const float Tlow = Tsh[0], Thigh = Tsh[1], S255 = S[256];
        const uint32_t local_trip = smem_u32(&trip[step][0]);
        #pragma unroll
        for (int r = 0; r < 4; ++r) {
            uint32_t dst;
            asm volatile("mapa.shared::cluster.u32 %0, %1, %2;"
                         : "=r"(dst) : "r"(local_trip), "r"(r));
            asm volatile("st.shared::cluster.f32 [%0], %1;"     :: "r"(dst), "f"(Tlow));
            asm volatile("st.shared::cluster.f32 [%0+4], %1;"   :: "r"(dst), "f"(Thigh));
            asm volatile("st.shared::cluster.f32 [%0+8], %1;"   :: "r"(dst), "f"(S255));
        }
    }
    // barrier.cluster: release/acquire — orders the remote stores above
    // before any post-wait read of trip[][]
    asm volatile("barrier.cluster.arrive.aligned;" ::: "memory");
    asm volatile("barrier.cluster.wait.aligned;" ::: "memory");

    // ---- Phase E: every CTA runs the scalar carry chain (redundantly) ----
    if (tid == 0) {
        float c0 = 1.f, c1 = 0.f;                // carry0 = (1, 0)
        #pragma unroll
        for (int s = 0; s < 4; ++s) {
            const float Tlow = trip[s][0], Thigh = trip[s][1], S255 = trip[s][2];
            const float E0 = __expf(10.f * c0), E1 = __expf(10.f * c1);
            const float iZ = 1.0f / ((E0 + E1) * (Tlow + Thigh));
            if (s == step) { ECiZ[0] = E0; ECiZ[1] = E1; ECiZ[2] = iZ; }
            c0 = (E0 * Tlow  + E1 * (Tlow  - S255)) * iZ;
            c1 = (E0 * Thigh + E1 * (Thigh + S255)) * iZ;
        }
    }
    __syncthreads();

    // ---- Phase F: outputs for my step, from local S ----
    if (tid < 256) {
        const float E0 = ECiZ[0], E1 = ECiZ[1], iZ = ECiZ[2];
        // c=0: bins m=d and m=d+256 ; c=1: bins m=d-1 and m=d+255
        float num = E0 * (S[1 + tid] + S[257 + tid])
                  + E1 * (S[tid]     + S[256 + tid]);
        out[step * 256 + tid] = num * iZ;
    }
    // Exit safety: all remote SMEM writes completed before the cluster
    // barrier, and no remote reads happen after it.
}

extern "C" void kernel_launch(void* const* d_in, const int* in_sizes, int n_in,
                              void* d_out, int out_size) {
    const float* a_emb = (const float*)d_in[0];   // [4, 256]
    const float* b_emb = (const float*)d_in[1];   // [4, 256]
    float* out = (float*)d_out;                   // [4, 256]
    (void)in_sizes; (void)n_in; (void)out_size;
    c4_cluster_kernel<<<4, 1024>>>(a_emb, b_emb, out);
}